// round 12
// baseline (speedup 1.0000x reference)
#include <cuda_runtime.h>
#include <math.h>

// Problem constants
#define BB 2
#define SS 2048
#define DD 1024
#define HH 16
#define DH 64
#define NQKV 3072
#define MM (BB * SS)   // 4096
#define SCALE_Q 0.125f // 64^-0.5

// Scratch (device globals, allocation-free)
static __device__ float g_q[BB * HH * SS * DH];   // [b,h,s,dh]
static __device__ float g_k[BB * HH * SS * DH];
static __device__ float g_v[BB * HH * SS * DH];
static __device__ float g_ao[MM * DD];            // [b,s,h*dh]

// ---------------------------------------------------------------------------
// Generic 128x128x16 fp32 tiled GEMM, 256 threads, 8x8 per thread.
// MODE 0: C = A@B + bias, scatter into g_q/g_k/g_v with q*SCALE.
// MODE 1: C = g_ao@B + bias -> C (out projection).
// ---------------------------------------------------------------------------
template <int MODE>
__global__ __launch_bounds__(256) void gemm_kernel(
    const float* __restrict__ A, const float* __restrict__ Bm,
    const float* __restrict__ bias, float* __restrict__ C,
    int M, int N, int K)
{
    __shared__ float As[16][128];   // A^T tile: As[k][m]
    __shared__ float Bs[16][128];   // Bs[k][n]

    const int tid = threadIdx.x;
    const int tx = tid & 15;
    const int ty = tid >> 4;
    const int bm = blockIdx.y << 7;
    const int bn = blockIdx.x << 7;

    const float* Ap = (MODE == 1) ? g_ao : A;

    float acc[8][8];
#pragma unroll
    for (int i = 0; i < 8; i++)
#pragma unroll
        for (int j = 0; j < 8; j++) acc[i][j] = 0.0f;

    for (int k0 = 0; k0 < K; k0 += 16) {
#pragma unroll
        for (int i = 0; i < 2; i++) {
            int f = tid + (i << 8);           // float4 index 0..511
            int ar = f >> 2, ac = (f & 3) << 2;
            float4 av = *reinterpret_cast<const float4*>(
                Ap + (size_t)(bm + ar) * K + k0 + ac);
            As[ac + 0][ar] = av.x;
            As[ac + 1][ar] = av.y;
            As[ac + 2][ar] = av.z;
            As[ac + 3][ar] = av.w;
            int br = f >> 5, bc = (f & 31) << 2;
            float4 bv = *reinterpret_cast<const float4*>(
                Bm + (size_t)(k0 + br) * N + bn + bc);
            *reinterpret_cast<float4*>(&Bs[br][bc]) = bv;
        }
        __syncthreads();
#pragma unroll
        for (int k = 0; k < 16; k++) {
            float ar[8], br[8];
#pragma unroll
            for (int i = 0; i < 8; i++) ar[i] = As[k][(ty << 3) + i];
#pragma unroll
            for (int j = 0; j < 8; j++) br[j] = Bs[k][(tx << 3) + j];
#pragma unroll
            for (int i = 0; i < 8; i++)
#pragma unroll
                for (int j = 0; j < 8; j++)
                    acc[i][j] = fmaf(ar[i], br[j], acc[i][j]);
        }
        __syncthreads();
    }

#pragma unroll
    for (int i = 0; i < 8; i++) {
        int m = bm + (ty << 3) + i;
#pragma unroll
        for (int j = 0; j < 8; j++) {
            int n = bn + (tx << 3) + j;
            float c = acc[i][j] + bias[n];
            if (MODE == 0) {
                int which = n >> 10;          // 0=q 1=k 2=v
                int rem = n & 1023;
                int h = rem >> 6;
                int dh = rem & 63;
                int b = m >> 11;
                int s = m & 2047;
                int idx = ((b * HH + h) * SS + s) * DH + dh;
                if (which == 0)      g_q[idx] = c * SCALE_Q;
                else if (which == 1) g_k[idx] = c;
                else                 g_v[idx] = c;
            } else {
                C[(size_t)m * N + n] = c;
            }
        }
    }
}

// ---------------------------------------------------------------------------
// Flash-attention: per block, 64 q-rows of one (b,h). BN=64 key tiles,
// online softmax, K-buffer reused for P. 256 threads as 16x16, 4x4 frags.
// ---------------------------------------------------------------------------
__global__ __launch_bounds__(256) void attn_kernel()
{
    extern __shared__ float smf[];
    float(*Qs)[65]  = reinterpret_cast<float(*)[65]>(smf);
    float(*KPs)[65] = reinterpret_cast<float(*)[65]>(smf + 64 * 65);
    float(*Vs)[65]  = reinterpret_cast<float(*)[65]>(smf + 2 * 64 * 65);

    const int tid = threadIdx.x;
    const int tx = tid & 15;
    const int ty = tid >> 4;
    const int bh = blockIdx.y;          // 0..31
    const int b = bh >> 4;
    const int h = bh & 15;
    const int qi0 = blockIdx.x << 6;

    const float* Qg = g_q + (size_t)bh * SS * DH;
    const float* Kg = g_k + (size_t)bh * SS * DH;
    const float* Vg = g_v + (size_t)bh * SS * DH;

    // Load Q tile (64x64)
#pragma unroll
    for (int i = 0; i < 4; i++) {
        int f = tid + (i << 8);         // float4 idx 0..1023
        int r = f >> 4, c = (f & 15) << 2;
        float4 v = *reinterpret_cast<const float4*>(
            Qg + (size_t)(qi0 + r) * DH + c);
        Qs[r][c] = v.x; Qs[r][c + 1] = v.y; Qs[r][c + 2] = v.z; Qs[r][c + 3] = v.w;
    }

    float m_i[4], l_i[4], o[4][4];
#pragma unroll
    for (int ii = 0; ii < 4; ii++) {
        m_i[ii] = -1e30f;
        l_i[ii] = 0.0f;
#pragma unroll
        for (int dd = 0; dd < 4; dd++) o[ii][dd] = 0.0f;
    }
    __syncthreads();

    const int i0 = ty << 2;
    const int j0 = tx << 2;

    for (int t = 0; t < SS / 64; t++) {
        const int kbase = t << 6;
#pragma unroll
        for (int i = 0; i < 4; i++) {
            int f = tid + (i << 8);
            int r = f >> 4, c = (f & 15) << 2;
            float4 kv = *reinterpret_cast<const float4*>(
                Kg + (size_t)(kbase + r) * DH + c);
            KPs[r][c] = kv.x; KPs[r][c + 1] = kv.y; KPs[r][c + 2] = kv.z; KPs[r][c + 3] = kv.w;
            float4 vv = *reinterpret_cast<const float4*>(
                Vg + (size_t)(kbase + r) * DH + c);
            Vs[r][c] = vv.x; Vs[r][c + 1] = vv.y; Vs[r][c + 2] = vv.z; Vs[r][c + 3] = vv.w;
        }
        __syncthreads();

        // S = Q @ K^T (64x64 tile, 4x4 frag)
        float s[4][4];
#pragma unroll
        for (int ii = 0; ii < 4; ii++)
#pragma unroll
            for (int jj = 0; jj < 4; jj++) s[ii][jj] = 0.0f;

#pragma unroll 4
        for (int d = 0; d < 64; d++) {
            float qr[4], kr[4];
#pragma unroll
            for (int ii = 0; ii < 4; ii++) qr[ii] = Qs[i0 + ii][d];
#pragma unroll
            for (int jj = 0; jj < 4; jj++) kr[jj] = KPs[j0 + jj][d];
#pragma unroll
            for (int ii = 0; ii < 4; ii++)
#pragma unroll
                for (int jj = 0; jj < 4; jj++)
                    s[ii][jj] = fmaf(qr[ii], kr[jj], s[ii][jj]);
        }

        // Online softmax update (rows owned by this ty; reduce across 16 tx)
#pragma unroll
        for (int ii = 0; ii < 4; ii++) {
            float mx = s[ii][0];
#pragma unroll
            for (int jj = 1; jj < 4; jj++) mx = fmaxf(mx, s[ii][jj]);
#pragma unroll
            for (int off = 8; off > 0; off >>= 1)
                mx = fmaxf(mx, __shfl_xor_sync(0xffffffffu, mx, off));
            float mnew = fmaxf(m_i[ii], mx);
            float al = __expf(m_i[ii] - mnew);
            float sum = 0.0f;
#pragma unroll
            for (int jj = 0; jj < 4; jj++) {
                float p = __expf(s[ii][jj] - mnew);
                s[ii][jj] = p;
                sum += p;
            }
#pragma unroll
            for (int off = 8; off > 0; off >>= 1)
                sum += __shfl_xor_sync(0xffffffffu, sum, off);
            l_i[ii] = l_i[ii] * al + sum;
            m_i[ii] = mnew;
#pragma unroll
            for (int dd = 0; dd < 4; dd++) o[ii][dd] *= al;
        }

        __syncthreads();   // all threads done reading K from KPs
#pragma unroll
        for (int ii = 0; ii < 4; ii++)
#pragma unroll
            for (int jj = 0; jj < 4; jj++)
                KPs[i0 + ii][j0 + jj] = s[ii][jj];
        __syncthreads();   // P visible

        // O += P @ V
#pragma unroll 4
        for (int n = 0; n < 64; n++) {
            float pr[4], vr[4];
#pragma unroll
            for (int ii = 0; ii < 4; ii++) pr[ii] = KPs[i0 + ii][n];
#pragma unroll
            for (int dd = 0; dd < 4; dd++) vr[dd] = Vs[n][j0 + dd];
#pragma unroll
            for (int ii = 0; ii < 4; ii++)
#pragma unroll
                for (int dd = 0; dd < 4; dd++)
                    o[ii][dd] = fmaf(pr[ii], vr[dd], o[ii][dd]);
        }
        __syncthreads();   // before next tile overwrites K/V
    }

    // Normalize + store into g_ao[(b*S+s)*D + h*64 + d]
#pragma unroll
    for (int ii = 0; ii < 4; ii++) {
        float inv = 1.0f / l_i[ii];
        int srow = qi0 + i0 + ii;
        size_t base = ((size_t)(b * SS + srow)) * DD + h * 64 + j0;
#pragma unroll
        for (int dd = 0; dd < 4; dd++)
            g_ao[base + dd] = o[ii][dd] * inv;
    }
}

// ---------------------------------------------------------------------------
extern "C" void kernel_launch(void* const* d_in, const int* in_sizes, int n_in,
                              void* d_out, int out_size)
{
    const float* x     = (const float*)d_in[0];
    const float* w_qkv = (const float*)d_in[1];
    const float* b_qkv = (const float*)d_in[2];
    const float* w_out = (const float*)d_in[3];
    const float* b_out = (const float*)d_in[4];
    float* out = (float*)d_out;

    // 1) QKV projection + scatter
    gemm_kernel<0><<<dim3(NQKV / 128, MM / 128), 256>>>(
        x, w_qkv, b_qkv, nullptr, MM, NQKV, DD);

    // 2) Attention
    const int attn_smem = 3 * 64 * 65 * (int)sizeof(float);   // 49920 B
    cudaFuncSetAttribute(attn_kernel,
                         cudaFuncAttributeMaxDynamicSharedMemorySize, attn_smem);
    attn_kernel<<<dim3(SS / 64, BB * HH), 256, attn_smem>>>();

    // 3) Output projection
    gemm_kernel<1><<<dim3(DD / 128, MM / 128), 256>>>(
        nullptr, w_out, b_out, out, MM, DD, DD);
}

// round 13
// speedup vs baseline: 1.0031x; 1.0031x over previous
#include <cuda_runtime.h>
#include <math.h>

// Problem constants
#define BB 2
#define SS 2048
#define DD 1024
#define HH 16
#define DH 64
#define NQKV 3072
#define MM (BB * SS)   // 4096
#define SCALE_Q 0.125f // 64^-0.5

// Scratch (device globals, allocation-free)
static __device__ float g_q[BB * HH * SS * DH];   // [b,h,s,dh]
static __device__ float g_k[BB * HH * SS * DH];
static __device__ float g_v[BB * HH * SS * DH];
static __device__ float g_ao[MM * DD];            // [b,s,h*dh]

// ---------------------------------------------------------------------------
// Generic 128x128x16 fp32 tiled GEMM, 256 threads, 8x8 per thread.
// MODE 0: C = A@B + bias, scatter into g_q/g_k/g_v with q*SCALE.
// MODE 1: C = g_ao@B + bias -> C (out projection).
// ---------------------------------------------------------------------------
template <int MODE>
__global__ __launch_bounds__(256) void gemm_kernel(
    const float* __restrict__ A, const float* __restrict__ Bm,
    const float* __restrict__ bias, float* __restrict__ C,
    int M, int N, int K)
{
    __shared__ float As[16][128];   // A^T tile: As[k][m]
    __shared__ float Bs[16][128];   // Bs[k][n]

    const int tid = threadIdx.x;
    const int tx = tid & 15;
    const int ty = tid >> 4;
    const int bm = blockIdx.y << 7;
    const int bn = blockIdx.x << 7;

    const float* Ap = (MODE == 1) ? g_ao : A;

    float acc[8][8];
#pragma unroll
    for (int i = 0; i < 8; i++)
#pragma unroll
        for (int j = 0; j < 8; j++) acc[i][j] = 0.0f;

    for (int k0 = 0; k0 < K; k0 += 16) {
#pragma unroll
        for (int i = 0; i < 2; i++) {
            int f = tid + (i << 8);           // float4 index 0..511
            int ar = f >> 2, ac = (f & 3) << 2;
            float4 av = *reinterpret_cast<const float4*>(
                Ap + (size_t)(bm + ar) * K + k0 + ac);
            As[ac + 0][ar] = av.x;
            As[ac + 1][ar] = av.y;
            As[ac + 2][ar] = av.z;
            As[ac + 3][ar] = av.w;
            int br = f >> 5, bc = (f & 31) << 2;
            float4 bv = *reinterpret_cast<const float4*>(
                Bm + (size_t)(k0 + br) * N + bn + bc);
            *reinterpret_cast<float4*>(&Bs[br][bc]) = bv;
        }
        __syncthreads();
#pragma unroll
        for (int k = 0; k < 16; k++) {
            float ar[8], br[8];
#pragma unroll
            for (int i = 0; i < 8; i++) ar[i] = As[k][(ty << 3) + i];
#pragma unroll
            for (int j = 0; j < 8; j++) br[j] = Bs[k][(tx << 3) + j];
#pragma unroll
            for (int i = 0; i < 8; i++)
#pragma unroll
                for (int j = 0; j < 8; j++)
                    acc[i][j] = fmaf(ar[i], br[j], acc[i][j]);
        }
        __syncthreads();
    }

#pragma unroll
    for (int i = 0; i < 8; i++) {
        int m = bm + (ty << 3) + i;
#pragma unroll
        for (int j = 0; j < 8; j++) {
            int n = bn + (tx << 3) + j;
            float c = acc[i][j] + bias[n];
            if (MODE == 0) {
                int which = n >> 10;          // 0=q 1=k 2=v
                int rem = n & 1023;
                int h = rem >> 6;
                int dh = rem & 63;
                int b = m >> 11;
                int s = m & 2047;
                int idx = ((b * HH + h) * SS + s) * DH + dh;
                if (which == 0)      g_q[idx] = c * SCALE_Q;
                else if (which == 1) g_k[idx] = c;
                else                 g_v[idx] = c;
            } else {
                C[(size_t)m * N + n] = c;
            }
        }
    }
}

// ---------------------------------------------------------------------------
// Flash-attention: per block, 64 q-rows of one (b,h). BN=64 key tiles,
// online softmax, K-buffer reused for P. 256 threads as 16x16, 4x4 frags.
// ---------------------------------------------------------------------------
__global__ __launch_bounds__(256) void attn_kernel()
{
    extern __shared__ float smf[];
    float(*Qs)[65]  = reinterpret_cast<float(*)[65]>(smf);
    float(*KPs)[65] = reinterpret_cast<float(*)[65]>(smf + 64 * 65);
    float(*Vs)[65]  = reinterpret_cast<float(*)[65]>(smf + 2 * 64 * 65);

    const int tid = threadIdx.x;
    const int tx = tid & 15;
    const int ty = tid >> 4;
    const int bh = blockIdx.y;          // 0..31
    const int b = bh >> 4;
    const int h = bh & 15;
    const int qi0 = blockIdx.x << 6;

    const float* Qg = g_q + (size_t)bh * SS * DH;
    const float* Kg = g_k + (size_t)bh * SS * DH;
    const float* Vg = g_v + (size_t)bh * SS * DH;

    // Load Q tile (64x64)
#pragma unroll
    for (int i = 0; i < 4; i++) {
        int f = tid + (i << 8);         // float4 idx 0..1023
        int r = f >> 4, c = (f & 15) << 2;
        float4 v = *reinterpret_cast<const float4*>(
            Qg + (size_t)(qi0 + r) * DH + c);
        Qs[r][c] = v.x; Qs[r][c + 1] = v.y; Qs[r][c + 2] = v.z; Qs[r][c + 3] = v.w;
    }

    float m_i[4], l_i[4], o[4][4];
#pragma unroll
    for (int ii = 0; ii < 4; ii++) {
        m_i[ii] = -1e30f;
        l_i[ii] = 0.0f;
#pragma unroll
        for (int dd = 0; dd < 4; dd++) o[ii][dd] = 0.0f;
    }
    __syncthreads();

    const int i0 = ty << 2;
    const int j0 = tx << 2;

    for (int t = 0; t < SS / 64; t++) {
        const int kbase = t << 6;
#pragma unroll
        for (int i = 0; i < 4; i++) {
            int f = tid + (i << 8);
            int r = f >> 4, c = (f & 15) << 2;
            float4 kv = *reinterpret_cast<const float4*>(
                Kg + (size_t)(kbase + r) * DH + c);
            KPs[r][c] = kv.x; KPs[r][c + 1] = kv.y; KPs[r][c + 2] = kv.z; KPs[r][c + 3] = kv.w;
            float4 vv = *reinterpret_cast<const float4*>(
                Vg + (size_t)(kbase + r) * DH + c);
            Vs[r][c] = vv.x; Vs[r][c + 1] = vv.y; Vs[r][c + 2] = vv.z; Vs[r][c + 3] = vv.w;
        }
        __syncthreads();

        // S = Q @ K^T (64x64 tile, 4x4 frag)
        float s[4][4];
#pragma unroll
        for (int ii = 0; ii < 4; ii++)
#pragma unroll
            for (int jj = 0; jj < 4; jj++) s[ii][jj] = 0.0f;

#pragma unroll 4
        for (int d = 0; d < 64; d++) {
            float qr[4], kr[4];
#pragma unroll
            for (int ii = 0; ii < 4; ii++) qr[ii] = Qs[i0 + ii][d];
#pragma unroll
            for (int jj = 0; jj < 4; jj++) kr[jj] = KPs[j0 + jj][d];
#pragma unroll
            for (int ii = 0; ii < 4; ii++)
#pragma unroll
                for (int jj = 0; jj < 4; jj++)
                    s[ii][jj] = fmaf(qr[ii], kr[jj], s[ii][jj]);
        }

        // Online softmax update (rows owned by this ty; reduce across 16 tx)
#pragma unroll
        for (int ii = 0; ii < 4; ii++) {
            float mx = s[ii][0];
#pragma unroll
            for (int jj = 1; jj < 4; jj++) mx = fmaxf(mx, s[ii][jj]);
#pragma unroll
            for (int off = 8; off > 0; off >>= 1)
                mx = fmaxf(mx, __shfl_xor_sync(0xffffffffu, mx, off));
            float mnew = fmaxf(m_i[ii], mx);
            float al = __expf(m_i[ii] - mnew);
            float sum = 0.0f;
#pragma unroll
            for (int jj = 0; jj < 4; jj++) {
                float p = __expf(s[ii][jj] - mnew);
                s[ii][jj] = p;
                sum += p;
            }
#pragma unroll
            for (int off = 8; off > 0; off >>= 1)
                sum += __shfl_xor_sync(0xffffffffu, sum, off);
            l_i[ii] = l_i[ii] * al + sum;
            m_i[ii] = mnew;
#pragma unroll
            for (int dd = 0; dd < 4; dd++) o[ii][dd] *= al;
        }

        __syncthreads();   // all threads done reading K from KPs
#pragma unroll
        for (int ii = 0; ii < 4; ii++)
#pragma unroll
            for (int jj = 0; jj < 4; jj++)
                KPs[i0 + ii][j0 + jj] = s[ii][jj];
        __syncthreads();   // P visible

        // O += P @ V
#pragma unroll 4
        for (int n = 0; n < 64; n++) {
            float pr[4], vr[4];
#pragma unroll
            for (int ii = 0; ii < 4; ii++) pr[ii] = KPs[i0 + ii][n];
#pragma unroll
            for (int dd = 0; dd < 4; dd++) vr[dd] = Vs[n][j0 + dd];
#pragma unroll
            for (int ii = 0; ii < 4; ii++)
#pragma unroll
                for (int dd = 0; dd < 4; dd++)
                    o[ii][dd] = fmaf(pr[ii], vr[dd], o[ii][dd]);
        }
        __syncthreads();   // before next tile overwrites K/V
    }

    // Normalize + store into g_ao[(b*S+s)*D + h*64 + d]
#pragma unroll
    for (int ii = 0; ii < 4; ii++) {
        float inv = 1.0f / l_i[ii];
        int srow = qi0 + i0 + ii;
        size_t base = ((size_t)(b * SS + srow)) * DD + h * 64 + j0;
#pragma unroll
        for (int dd = 0; dd < 4; dd++)
            g_ao[base + dd] = o[ii][dd] * inv;
    }
}

// ---------------------------------------------------------------------------
extern "C" void kernel_launch(void* const* d_in, const int* in_sizes, int n_in,
                              void* d_out, int out_size)
{
    const float* x     = (const float*)d_in[0];
    const float* w_qkv = (const float*)d_in[1];
    const float* b_qkv = (const float*)d_in[2];
    const float* w_out = (const float*)d_in[3];
    const float* b_out = (const float*)d_in[4];
    float* out = (float*)d_out;

    // 1) QKV projection + scatter
    gemm_kernel<0><<<dim3(NQKV / 128, MM / 128), 256>>>(
        x, w_qkv, b_qkv, nullptr, MM, NQKV, DD);

    // 2) Attention
    const int attn_smem = 3 * 64 * 65 * (int)sizeof(float);   // 49920 B
    cudaFuncSetAttribute(attn_kernel,
                         cudaFuncAttributeMaxDynamicSharedMemorySize, attn_smem);
    attn_kernel<<<dim3(SS / 64, BB * HH), 256, attn_smem>>>();

    // 3) Output projection
    gemm_kernel<1><<<dim3(DD / 128, MM / 128), 256>>>(
        nullptr, w_out, b_out, out, MM, DD, DD);
}